// round 1
// baseline (speedup 1.0000x reference)
#include <cuda_runtime.h>
#include <math.h>
#include <stdint.h>

// Problem sizes (fixed)
#define BATCH 2
#define SEQ   4096
#define DIM   1024
#define MTOT  (BATCH * SEQ)     // 8192
#define DE    (2 * DIM)         // 2048  (cos || sin concatenated)

// ---------------- scratch (device globals; no allocation allowed) ----------
__device__ float g_Q [MTOT * DIM];
__device__ float g_K [MTOT * DIM];
__device__ float g_V [MTOT * DIM];
__device__ float g_Qe[MTOT * DE];
__device__ float g_Ke[MTOT * DE];
__device__ float g_S [(size_t)BATCH * SEQ * SEQ];   // scores / weights (134 MB)

// ---------------------------------------------------------------------------
// SGEMM NT: C[M,N] = A[M,K] * B[N,K]^T (+ bias[N]).  A,B row-major, K-contig.
// 128x128 block tile, BK=16, 256 threads, 8x8 per-thread, register prefetch.
// M,N multiples of 128; K multiple of 16 (always true here).
// ---------------------------------------------------------------------------
__global__ void __launch_bounds__(256, 2)
sgemm_nt(const float* __restrict__ A, const float* __restrict__ B,
         const float* __restrict__ bias, float* __restrict__ C,
         int M, int N, int K,
         size_t strA, size_t strB, size_t strC)
{
    constexpr int BM = 128, BN = 128, BK = 16;
    __shared__ float As[BK][BM + 4];
    __shared__ float Bs[BK][BN + 4];

    A += strA * blockIdx.z;
    B += strB * blockIdx.z;
    C += strC * blockIdx.z;

    const int tid   = threadIdx.x;
    const int row_l = tid >> 2;   // 0..63
    const int c4    = tid & 3;    // 0..3  (which float4 in the 16-wide K slice)

    const float* Ag = A + ((size_t)blockIdx.y * BM + row_l) * K + c4 * 4;
    const float* Bg = B + ((size_t)blockIdx.x * BN + row_l) * K + c4 * 4;

    float4 ra0 = *(const float4*)Ag;
    float4 ra1 = *(const float4*)(Ag + (size_t)64 * K);
    float4 rb0 = *(const float4*)Bg;
    float4 rb1 = *(const float4*)(Bg + (size_t)64 * K);

    const int ty = tid >> 4;   // 0..15
    const int tx = tid & 15;   // 0..15

    float acc[8][8];
#pragma unroll
    for (int i = 0; i < 8; i++)
#pragma unroll
        for (int j = 0; j < 8; j++) acc[i][j] = 0.0f;

    for (int k0 = 0; k0 < K; k0 += BK) {
        // stash prefetched tile into smem (transposed: [k][row])
        As[c4 * 4 + 0][row_l]      = ra0.x;
        As[c4 * 4 + 1][row_l]      = ra0.y;
        As[c4 * 4 + 2][row_l]      = ra0.z;
        As[c4 * 4 + 3][row_l]      = ra0.w;
        As[c4 * 4 + 0][row_l + 64] = ra1.x;
        As[c4 * 4 + 1][row_l + 64] = ra1.y;
        As[c4 * 4 + 2][row_l + 64] = ra1.z;
        As[c4 * 4 + 3][row_l + 64] = ra1.w;
        Bs[c4 * 4 + 0][row_l]      = rb0.x;
        Bs[c4 * 4 + 1][row_l]      = rb0.y;
        Bs[c4 * 4 + 2][row_l]      = rb0.z;
        Bs[c4 * 4 + 3][row_l]      = rb0.w;
        Bs[c4 * 4 + 0][row_l + 64] = rb1.x;
        Bs[c4 * 4 + 1][row_l + 64] = rb1.y;
        Bs[c4 * 4 + 2][row_l + 64] = rb1.z;
        Bs[c4 * 4 + 3][row_l + 64] = rb1.w;
        __syncthreads();

        if (k0 + BK < K) {   // prefetch next K-slice into registers
            Ag += BK; Bg += BK;
            ra0 = *(const float4*)Ag;
            ra1 = *(const float4*)(Ag + (size_t)64 * K);
            rb0 = *(const float4*)Bg;
            rb1 = *(const float4*)(Bg + (size_t)64 * K);
        }

#pragma unroll
        for (int kk = 0; kk < BK; kk++) {
            float a[8], b[8];
            *(float4*)&a[0] = *(const float4*)&As[kk][ty * 8];
            *(float4*)&a[4] = *(const float4*)&As[kk][ty * 8 + 4];
            *(float4*)&b[0] = *(const float4*)&Bs[kk][tx * 8];
            *(float4*)&b[4] = *(const float4*)&Bs[kk][tx * 8 + 4];
#pragma unroll
            for (int i = 0; i < 8; i++)
#pragma unroll
                for (int j = 0; j < 8; j++)
                    acc[i][j] = fmaf(a[i], b[j], acc[i][j]);
        }
        __syncthreads();
    }

    const int crow = blockIdx.y * BM + ty * 8;
    const int ccol = blockIdx.x * BN + tx * 8;
    float bv[8];
    if (bias) {
        *(float4*)&bv[0] = *(const float4*)&bias[ccol];
        *(float4*)&bv[4] = *(const float4*)&bias[ccol + 4];
    } else {
#pragma unroll
        for (int j = 0; j < 8; j++) bv[j] = 0.0f;
    }
#pragma unroll
    for (int i = 0; i < 8; i++) {
        float4 o0 = { acc[i][0] + bv[0], acc[i][1] + bv[1],
                      acc[i][2] + bv[2], acc[i][3] + bv[3] };
        float4 o1 = { acc[i][4] + bv[4], acc[i][5] + bv[5],
                      acc[i][6] + bv[6], acc[i][7] + bv[7] };
        *(float4*)&C[(size_t)(crow + i) * N + ccol]     = o0;
        *(float4*)&C[(size_t)(crow + i) * N + ccol + 4] = o1;
    }
}

// ---------------------------------------------------------------------------
// SGEMM NN: C[M,N] = A[M,K] * B[K,N].  (for weights @ V)
// ---------------------------------------------------------------------------
__global__ void __launch_bounds__(256, 2)
sgemm_nn(const float* __restrict__ A, const float* __restrict__ B,
         float* __restrict__ C,
         int M, int N, int K,
         size_t strA, size_t strB, size_t strC)
{
    constexpr int BM = 128, BN = 128, BK = 16;
    __shared__ float As[BK][BM + 4];
    __shared__ float Bs[BK][BN + 4];

    A += strA * blockIdx.z;
    B += strB * blockIdx.z;
    C += strC * blockIdx.z;

    const int tid   = threadIdx.x;
    // A loader (same as NT)
    const int row_a = tid >> 2;
    const int c4a   = tid & 3;
    const float* Ag = A + ((size_t)blockIdx.y * BM + row_a) * K + c4a * 4;
    // B loader: tile is BK rows x BN cols of row-major [K,N]
    const int row_b = tid >> 5;   // 0..7   (i = tid:      rows 0..7)
    const int c4b   = tid & 31;   // 0..31  (i = tid+256:  rows 8..15)
    const float* Bg = B + (size_t)row_b * N + (size_t)blockIdx.x * BN + c4b * 4;

    float4 ra0 = *(const float4*)Ag;
    float4 ra1 = *(const float4*)(Ag + (size_t)64 * K);
    float4 rb0 = *(const float4*)Bg;
    float4 rb1 = *(const float4*)(Bg + (size_t)8 * N);

    const int ty = tid >> 4;
    const int tx = tid & 15;

    float acc[8][8];
#pragma unroll
    for (int i = 0; i < 8; i++)
#pragma unroll
        for (int j = 0; j < 8; j++) acc[i][j] = 0.0f;

    for (int k0 = 0; k0 < K; k0 += BK) {
        As[c4a * 4 + 0][row_a]      = ra0.x;
        As[c4a * 4 + 1][row_a]      = ra0.y;
        As[c4a * 4 + 2][row_a]      = ra0.z;
        As[c4a * 4 + 3][row_a]      = ra0.w;
        As[c4a * 4 + 0][row_a + 64] = ra1.x;
        As[c4a * 4 + 1][row_a + 64] = ra1.y;
        As[c4a * 4 + 2][row_a + 64] = ra1.z;
        As[c4a * 4 + 3][row_a + 64] = ra1.w;
        *(float4*)&Bs[row_b][c4b * 4]     = rb0;
        *(float4*)&Bs[row_b + 8][c4b * 4] = rb1;
        __syncthreads();

        if (k0 + BK < K) {
            Ag += BK;
            Bg += (size_t)BK * N;
            ra0 = *(const float4*)Ag;
            ra1 = *(const float4*)(Ag + (size_t)64 * K);
            rb0 = *(const float4*)Bg;
            rb1 = *(const float4*)(Bg + (size_t)8 * N);
        }

#pragma unroll
        for (int kk = 0; kk < BK; kk++) {
            float a[8], b[8];
            *(float4*)&a[0] = *(const float4*)&As[kk][ty * 8];
            *(float4*)&a[4] = *(const float4*)&As[kk][ty * 8 + 4];
            *(float4*)&b[0] = *(const float4*)&Bs[kk][tx * 8];
            *(float4*)&b[4] = *(const float4*)&Bs[kk][tx * 8 + 4];
#pragma unroll
            for (int i = 0; i < 8; i++)
#pragma unroll
                for (int j = 0; j < 8; j++)
                    acc[i][j] = fmaf(a[i], b[j], acc[i][j]);
        }
        __syncthreads();
    }

    const int crow = blockIdx.y * BM + ty * 8;
    const int ccol = blockIdx.x * BN + tx * 8;
#pragma unroll
    for (int i = 0; i < 8; i++) {
        float4 o0 = { acc[i][0], acc[i][1], acc[i][2], acc[i][3] };
        float4 o1 = { acc[i][4], acc[i][5], acc[i][6], acc[i][7] };
        *(float4*)&C[(size_t)(crow + i) * N + ccol]     = o0;
        *(float4*)&C[(size_t)(crow + i) * N + ccol + 4] = o1;
    }
}

// ---------------------------------------------------------------------------
// theta: Qe = [cos(Q*inv_wl + pb) | sin(...)], Ke likewise.
// ---------------------------------------------------------------------------
__global__ void __launch_bounds__(256)
theta_kernel(const float* __restrict__ Q, const float* __restrict__ K,
             const float* __restrict__ pb,
             float* __restrict__ Qe, float* __restrict__ Ke)
{
    const int idx = blockIdx.x * blockDim.x + threadIdx.x;   // < MTOT*DIM
    const int d = idx & (DIM - 1);
    const int m = idx >> 10;                                  // DIM = 1024
    const float WLC = (float)(6.283185307179586 / (double)DIM);
    float wl  = (float)(d + 1) * WLC;
    float inv = 1.0f / (wl + 1e-8f);
    float p   = pb[d];

    float sq, cq, sk, ck;
    sincosf(fmaf(Q[idx], inv, p), &sq, &cq);
    sincosf(fmaf(K[idx], inv, p), &sk, &ck);

    size_t base = (size_t)m * DE;
    Qe[base + d]        = cq;
    Qe[base + DIM + d]  = sq;
    Ke[base + d]        = ck;
    Ke[base + DIM + d]  = sk;
}

// ---------------------------------------------------------------------------
// softmax over rows of g_S (row length SEQ), logits scaled by 1/32.
// one block (256 threads) per row; 16 elems/thread kept in registers.
// ---------------------------------------------------------------------------
__global__ void __launch_bounds__(256)
softmax_rows(float* __restrict__ S)
{
    __shared__ float sm[8];
    float* p = S + (size_t)blockIdx.x * SEQ;
    float4* p4 = (float4*)p;
    const int t    = threadIdx.x;
    const int lane = t & 31;
    const int wid  = t >> 5;
    const float SCALE = 0.03125f;   // 1/sqrt(1024)

    float v[16];
    float mx = -1e30f;
#pragma unroll
    for (int i = 0; i < 4; i++) {
        float4 x = p4[t + i * 256];
        v[4*i+0] = x.x * SCALE; v[4*i+1] = x.y * SCALE;
        v[4*i+2] = x.z * SCALE; v[4*i+3] = x.w * SCALE;
        mx = fmaxf(mx, fmaxf(fmaxf(v[4*i+0], v[4*i+1]),
                             fmaxf(v[4*i+2], v[4*i+3])));
    }
#pragma unroll
    for (int off = 16; off >= 1; off >>= 1)
        mx = fmaxf(mx, __shfl_xor_sync(0xffffffffu, mx, off));
    if (lane == 0) sm[wid] = mx;
    __syncthreads();
    mx = sm[0];
#pragma unroll
    for (int w = 1; w < 8; w++) mx = fmaxf(mx, sm[w]);
    __syncthreads();

    float sum = 0.0f;
#pragma unroll
    for (int i = 0; i < 16; i++) { v[i] = expf(v[i] - mx); sum += v[i]; }
#pragma unroll
    for (int off = 16; off >= 1; off >>= 1)
        sum += __shfl_xor_sync(0xffffffffu, sum, off);
    if (lane == 0) sm[wid] = sum;
    __syncthreads();
    sum = sm[0];
#pragma unroll
    for (int w = 1; w < 8; w++) sum += sm[w];
    float inv = 1.0f / sum;

#pragma unroll
    for (int i = 0; i < 4; i++) {
        float4 o = { v[4*i+0]*inv, v[4*i+1]*inv, v[4*i+2]*inv, v[4*i+3]*inv };
        p4[t + i * 256] = o;
    }
}

// ---------------------------------------------------------------------------
extern "C" void kernel_launch(void* const* d_in, const int* in_sizes, int n_in,
                              void* d_out, int out_size)
{
    const float* x  = (const float*)d_in[0];
    const float* Wq = (const float*)d_in[1];
    const float* bq = (const float*)d_in[2];
    const float* Wk = (const float*)d_in[3];
    const float* bk = (const float*)d_in[4];
    const float* Wv = (const float*)d_in[5];
    const float* bv = (const float*)d_in[6];
    const float* pb = (const float*)d_in[7];
    float* out = (float*)d_out;

    float *Q, *K, *V, *Qe, *Ke, *Sm;
    cudaGetSymbolAddress((void**)&Q,  g_Q);
    cudaGetSymbolAddress((void**)&K,  g_K);
    cudaGetSymbolAddress((void**)&V,  g_V);
    cudaGetSymbolAddress((void**)&Qe, g_Qe);
    cudaGetSymbolAddress((void**)&Ke, g_Ke);
    cudaGetSymbolAddress((void**)&Sm, g_S);

    // 1) QKV projections: C[8192,1024] = x @ W^T + b
    dim3 gProj(DIM / 128, MTOT / 128, 1);
    sgemm_nt<<<gProj, 256>>>(x, Wq, bq, Q, MTOT, DIM, DIM, 0, 0, 0);
    sgemm_nt<<<gProj, 256>>>(x, Wk, bk, K, MTOT, DIM, DIM, 0, 0, 0);
    sgemm_nt<<<gProj, 256>>>(x, Wv, bv, V, MTOT, DIM, DIM, 0, 0, 0);

    // 2) theta -> [cos | sin]
    theta_kernel<<<(MTOT * DIM) / 256, 256>>>(Q, K, pb, Qe, Ke);

    // 3) sim = Qe @ Ke^T per batch (K-dim 2048)
    dim3 gSim(SEQ / 128, SEQ / 128, BATCH);
    sgemm_nt<<<gSim, 256>>>(Qe, Ke, nullptr, Sm, SEQ, SEQ, DE,
                            (size_t)SEQ * DE, (size_t)SEQ * DE,
                            (size_t)SEQ * SEQ);

    // 4) softmax(sim / 32) rows
    softmax_rows<<<BATCH * SEQ, 256>>>(Sm);

    // 5) out = weights @ V per batch
    dim3 gPV(DIM / 128, SEQ / 128, BATCH);
    sgemm_nn<<<gPV, 256>>>(Sm, V, out, SEQ, DIM, SEQ,
                           (size_t)SEQ * SEQ, (size_t)SEQ * DIM,
                           (size_t)SEQ * DIM);
}

// round 3
// speedup vs baseline: 2.0016x; 2.0016x over previous
#include <cuda_runtime.h>
#include <math.h>
#include <stdint.h>

// Problem sizes (fixed)
#define BATCH 2
#define SEQ   4096
#define DIM   1024
#define MTOT  (BATCH * SEQ)     // 8192
#define DE    (2 * DIM)         // 2048  (cos || sin concatenated)

// ---------------- scratch (device globals; no allocation allowed) ----------
__device__ float g_Q [MTOT * DIM];
__device__ float g_K [MTOT * DIM];
__device__ float g_V [MTOT * DIM];
__device__ float g_Vt[MTOT * DIM];                  // V transposed per batch [DIM, SEQ]
__device__ float g_Qe[MTOT * DE];
__device__ float g_Ke[MTOT * DE];
__device__ float g_S [(size_t)BATCH * SEQ * SEQ];   // scores / weights (134 MB)

// ============================ helpers =======================================
__device__ __forceinline__ uint32_t smem_u32(const void* p) {
    uint32_t a;
    asm("{ .reg .u64 t; cvta.to.shared.u64 t, %1; cvt.u32.u64 %0, t; }"
        : "=r"(a) : "l"(p));
    return a;
}

__device__ __forceinline__ float to_tf32(float x) {
    uint32_t u;
    asm("cvt.rna.tf32.f32 %0, %1;" : "=r"(u) : "f"(x));
    return __uint_as_float(u);
}

__device__ __forceinline__ void cpasync16(uint32_t saddr, const void* gaddr) {
    asm volatile("cp.async.cg.shared.global [%0], [%1], 16;"
                 :: "r"(saddr), "l"(gaddr) : "memory");
}

__device__ __forceinline__ void mma_tf32(float c[4], const uint32_t a[4],
                                         const uint32_t b[2]) {
    asm volatile(
        "mma.sync.aligned.m16n8k8.row.col.f32.tf32.tf32.f32 "
        "{%0,%1,%2,%3}, {%4,%5,%6,%7}, {%8,%9}, {%0,%1,%2,%3};"
        : "+f"(c[0]), "+f"(c[1]), "+f"(c[2]), "+f"(c[3])
        : "r"(a[0]), "r"(a[1]), "r"(a[2]), "r"(a[3]),
          "r"(b[0]), "r"(b[1]));
}

// ============================================================================
// tf32 tensor-core NT GEMM via mma.sync: C[M,N] = A[M,K] @ B[N,K]^T, fp32 out.
// 128x128x32 CTA tile, 3-stage cp.async pipeline, 256 threads (8 warps),
// warp tile 64x32 (warp grid 2x4), mma.m16n8k8.
// Smem rows padded to 36 floats (conflict-free for fragment loads).
// Inputs assumed pre-rounded to tf32. K multiple of 32; tiles full.
// ============================================================================
#define MMA_STAGE_BYTES  36864              // 2 * 128 * 36 * 4
#define MMA_SMEM_BYTES   (3 * MMA_STAGE_BYTES)

__global__ void __launch_bounds__(256, 1)
mma_nt_tf32(const float* __restrict__ A, const float* __restrict__ B,
            float* __restrict__ C, int Nld, int K,
            size_t strA, size_t strB, size_t strC)
{
    extern __shared__ float dynsmem[];
    const uint32_t sb = smem_u32(dynsmem);

    const int tid  = threadIdx.x;
    const int wid  = tid >> 5;
    const int lane = tid & 31;

    A += strA * blockIdx.z;
    B += strB * blockIdx.z;
    C += strC * blockIdx.z;
    const int tileM = blockIdx.y * 128;
    const int tileN = blockIdx.x * 128;

    // ---- loader mapping: thread covers rows baseRow + 32*i (i<4), 16B seg
    const int baseRow = tid >> 3;      // 0..31
    const int seg     = tid & 7;       // 0..7
    const float* Ath = A + (size_t)(tileM + baseRow) * K + seg * 4;
    const float* Bth = B + (size_t)(tileN + baseRow) * K + seg * 4;
    const uint32_t thoff = (uint32_t)(baseRow * 144 + seg * 16);

#define ISSUE_STAGE(KT, S) do {                                               \
    uint32_t _sa = sb + (uint32_t)(S) * MMA_STAGE_BYTES + thoff;              \
    const float* _ga = Ath + (size_t)(KT) * 32;                               \
    const float* _gb = Bth + (size_t)(KT) * 32;                               \
    _Pragma("unroll")                                                         \
    for (int _i = 0; _i < 4; _i++)                                            \
        cpasync16(_sa + _i * (32u * 144u), _ga + (size_t)_i * 32 * K);        \
    _Pragma("unroll")                                                         \
    for (int _i = 0; _i < 4; _i++)                                            \
        cpasync16(_sa + 18432u + _i * (32u * 144u), _gb + (size_t)_i * 32 * K); \
    asm volatile("cp.async.commit_group;" ::: "memory");                      \
} while (0)

    const int nkt = K >> 5;
    ISSUE_STAGE(0, 0);
    ISSUE_STAGE(1, 1);

    // ---- compute mapping
    const int warp_m = wid >> 2;       // 0..1  -> 64 rows
    const int warp_n = wid & 3;        // 0..3  -> 32 cols
    const int g   = lane >> 2;         // 0..7
    const int tig = lane & 3;          // 0..3

    float acc[4][4][4];
#pragma unroll
    for (int mi = 0; mi < 4; mi++)
#pragma unroll
        for (int nj = 0; nj < 4; nj++)
#pragma unroll
            for (int r = 0; r < 4; r++) acc[mi][nj][r] = 0.0f;

    int s = 0;   // stage of tile kt
    for (int kt = 0; kt < nkt; ++kt) {
        if (kt + 2 < nkt) {
            asm volatile("cp.async.wait_group 1;" ::: "memory");
        } else {
            asm volatile("cp.async.wait_group 0;" ::: "memory");
        }
        __syncthreads();

        if (kt + 2 < nkt) {
            const int s2 = (s + 2 >= 3) ? (s - 1) : (s + 2);
            ISSUE_STAGE(kt + 2, s2);
        }

        const float* sA = dynsmem + s * (MMA_STAGE_BYTES / 4);
        const float* sB = sA + 4608;

#pragma unroll
        for (int ks = 0; ks < 4; ++ks) {
            const int kk0 = ks * 8 + tig;
            uint32_t afr[4][4];
#pragma unroll
            for (int mi = 0; mi < 4; mi++) {
                const float* pa = sA + (size_t)(warp_m * 64 + mi * 16 + g) * 36;
                afr[mi][0] = __float_as_uint(pa[kk0]);
                afr[mi][1] = __float_as_uint(pa[8 * 36 + kk0]);
                afr[mi][2] = __float_as_uint(pa[kk0 + 4]);
                afr[mi][3] = __float_as_uint(pa[8 * 36 + kk0 + 4]);
            }
            uint32_t bfr[4][2];
#pragma unroll
            for (int nj = 0; nj < 4; nj++) {
                const float* pb = sB + (size_t)(warp_n * 32 + nj * 8 + g) * 36;
                bfr[nj][0] = __float_as_uint(pb[kk0]);
                bfr[nj][1] = __float_as_uint(pb[kk0 + 4]);
            }
#pragma unroll
            for (int mi = 0; mi < 4; mi++)
#pragma unroll
                for (int nj = 0; nj < 4; nj++)
                    mma_tf32(acc[mi][nj], afr[mi], bfr[nj]);
        }
        __syncthreads();
        s = (s + 1 == 3) ? 0 : (s + 1);
    }
#undef ISSUE_STAGE

    // ---- epilogue: direct fp32 stores (float2 per fragment row)
#pragma unroll
    for (int mi = 0; mi < 4; mi++) {
        const int row0 = tileM + warp_m * 64 + mi * 16 + g;
#pragma unroll
        for (int nj = 0; nj < 4; nj++) {
            const int col = tileN + warp_n * 32 + nj * 8 + 2 * tig;
            float2 lo = { acc[mi][nj][0], acc[mi][nj][1] };
            float2 hi = { acc[mi][nj][2], acc[mi][nj][3] };
            *(float2*)(C + (size_t)row0 * Nld + col)       = lo;
            *(float2*)(C + (size_t)(row0 + 8) * Nld + col) = hi;
        }
    }
}

// ---------------------------------------------------------------------------
// SGEMM NT (fp32 FFMA): C[M,N] = A[M,K] * B[N,K]^T (+ bias[N]).  QKV only.
// ---------------------------------------------------------------------------
__global__ void __launch_bounds__(256, 2)
sgemm_nt(const float* __restrict__ A, const float* __restrict__ B,
         const float* __restrict__ bias, float* __restrict__ C,
         int M, int N, int K)
{
    constexpr int BM = 128, BN = 128, BK = 16;
    __shared__ float As[BK][BM + 4];
    __shared__ float Bs[BK][BN + 4];

    const int tid   = threadIdx.x;
    const int row_l = tid >> 2;
    const int c4    = tid & 3;

    const float* Ag = A + ((size_t)blockIdx.y * BM + row_l) * K + c4 * 4;
    const float* Bg = B + ((size_t)blockIdx.x * BN + row_l) * K + c4 * 4;

    float4 ra0 = *(const float4*)Ag;
    float4 ra1 = *(const float4*)(Ag + (size_t)64 * K);
    float4 rb0 = *(const float4*)Bg;
    float4 rb1 = *(const float4*)(Bg + (size_t)64 * K);

    const int ty = tid >> 4;
    const int tx = tid & 15;

    float acc[8][8];
#pragma unroll
    for (int i = 0; i < 8; i++)
#pragma unroll
        for (int j = 0; j < 8; j++) acc[i][j] = 0.0f;

    for (int k0 = 0; k0 < K; k0 += BK) {
        As[c4 * 4 + 0][row_l]      = ra0.x;
        As[c4 * 4 + 1][row_l]      = ra0.y;
        As[c4 * 4 + 2][row_l]      = ra0.z;
        As[c4 * 4 + 3][row_l]      = ra0.w;
        As[c4 * 4 + 0][row_l + 64] = ra1.x;
        As[c4 * 4 + 1][row_l + 64] = ra1.y;
        As[c4 * 4 + 2][row_l + 64] = ra1.z;
        As[c4 * 4 + 3][row_l + 64] = ra1.w;
        Bs[c4 * 4 + 0][row_l]      = rb0.x;
        Bs[c4 * 4 + 1][row_l]      = rb0.y;
        Bs[c4 * 4 + 2][row_l]      = rb0.z;
        Bs[c4 * 4 + 3][row_l]      = rb0.w;
        Bs[c4 * 4 + 0][row_l + 64] = rb1.x;
        Bs[c4 * 4 + 1][row_l + 64] = rb1.y;
        Bs[c4 * 4 + 2][row_l + 64] = rb1.z;
        Bs[c4 * 4 + 3][row_l + 64] = rb1.w;
        __syncthreads();

        if (k0 + BK < K) {
            Ag += BK; Bg += BK;
            ra0 = *(const float4*)Ag;
            ra1 = *(const float4*)(Ag + (size_t)64 * K);
            rb0 = *(const float4*)Bg;
            rb1 = *(const float4*)(Bg + (size_t)64 * K);
        }

#pragma unroll
        for (int kk = 0; kk < BK; kk++) {
            float a[8], b[8];
            *(float4*)&a[0] = *(const float4*)&As[kk][ty * 8];
            *(float4*)&a[4] = *(const float4*)&As[kk][ty * 8 + 4];
            *(float4*)&b[0] = *(const float4*)&Bs[kk][tx * 8];
            *(float4*)&b[4] = *(const float4*)&Bs[kk][tx * 8 + 4];
#pragma unroll
            for (int i = 0; i < 8; i++)
#pragma unroll
                for (int j = 0; j < 8; j++)
                    acc[i][j] = fmaf(a[i], b[j], acc[i][j]);
        }
        __syncthreads();
    }

    const int crow = blockIdx.y * BM + ty * 8;
    const int ccol = blockIdx.x * BN + tx * 8;
    float bv[8];
    *(float4*)&bv[0] = *(const float4*)&bias[ccol];
    *(float4*)&bv[4] = *(const float4*)&bias[ccol + 4];
#pragma unroll
    for (int i = 0; i < 8; i++) {
        float4 o0 = { acc[i][0] + bv[0], acc[i][1] + bv[1],
                      acc[i][2] + bv[2], acc[i][3] + bv[3] };
        float4 o1 = { acc[i][4] + bv[4], acc[i][5] + bv[5],
                      acc[i][6] + bv[6], acc[i][7] + bv[7] };
        *(float4*)&C[(size_t)(crow + i) * N + ccol]     = o0;
        *(float4*)&C[(size_t)(crow + i) * N + ccol + 4] = o1;
    }
}

// ---------------------------------------------------------------------------
// theta: Qe = [cos(Q*inv_wl + pb) | sin(...)], Ke likewise; tf32-rounded.
// ---------------------------------------------------------------------------
__global__ void __launch_bounds__(256)
theta_kernel(const float* __restrict__ Q, const float* __restrict__ K,
             const float* __restrict__ pb,
             float* __restrict__ Qe, float* __restrict__ Ke)
{
    const int idx = blockIdx.x * blockDim.x + threadIdx.x;
    const int d = idx & (DIM - 1);
    const int m = idx >> 10;
    const float WLC = (float)(6.283185307179586 / (double)DIM);
    float wl  = (float)(d + 1) * WLC;
    float inv = 1.0f / (wl + 1e-8f);
    float p   = pb[d];

    float sq, cq, sk, ck;
    sincosf(fmaf(Q[idx], inv, p), &sq, &cq);
    sincosf(fmaf(K[idx], inv, p), &sk, &ck);

    size_t base = (size_t)m * DE;
    Qe[base + d]        = to_tf32(cq);
    Qe[base + DIM + d]  = to_tf32(sq);
    Ke[base + d]        = to_tf32(ck);
    Ke[base + DIM + d]  = to_tf32(sk);
}

// ---------------------------------------------------------------------------
// V transpose per batch (+ tf32 rounding): Vt[b][n][s] = V[b][s][n]
// ---------------------------------------------------------------------------
__global__ void __launch_bounds__(256)
transpose_round(const float* __restrict__ V, float* __restrict__ Vt)
{
    __shared__ float t[32][33];
    const int b  = blockIdx.z;
    const int s0 = blockIdx.y * 32;
    const int n0 = blockIdx.x * 32;
    V  += (size_t)b * SEQ * DIM;
    Vt += (size_t)b * DIM * SEQ;
    const int x = threadIdx.x, y = threadIdx.y;   // 32 x 8
#pragma unroll
    for (int i = 0; i < 32; i += 8)
        t[y + i][x] = V[(size_t)(s0 + y + i) * DIM + n0 + x];
    __syncthreads();
#pragma unroll
    for (int i = 0; i < 32; i += 8)
        Vt[(size_t)(n0 + y + i) * SEQ + s0 + x] = to_tf32(t[x][y + i]);
}

// ---------------------------------------------------------------------------
// softmax rows (len SEQ), logits /32; outputs tf32-rounded weights.
// ---------------------------------------------------------------------------
__global__ void __launch_bounds__(256)
softmax_rows(float* __restrict__ S)
{
    __shared__ float sm[8];
    float* p = S + (size_t)blockIdx.x * SEQ;
    float4* p4 = (float4*)p;
    const int t    = threadIdx.x;
    const int lane = t & 31;
    const int wid  = t >> 5;
    const float SCALE = 0.03125f;

    float v[16];
    float mx = -1e30f;
#pragma unroll
    for (int i = 0; i < 4; i++) {
        float4 x = p4[t + i * 256];
        v[4*i+0] = x.x * SCALE; v[4*i+1] = x.y * SCALE;
        v[4*i+2] = x.z * SCALE; v[4*i+3] = x.w * SCALE;
        mx = fmaxf(mx, fmaxf(fmaxf(v[4*i+0], v[4*i+1]),
                             fmaxf(v[4*i+2], v[4*i+3])));
    }
#pragma unroll
    for (int off = 16; off >= 1; off >>= 1)
        mx = fmaxf(mx, __shfl_xor_sync(0xffffffffu, mx, off));
    if (lane == 0) sm[wid] = mx;
    __syncthreads();
    mx = sm[0];
#pragma unroll
    for (int w = 1; w < 8; w++) mx = fmaxf(mx, sm[w]);
    __syncthreads();

    float sum = 0.0f;
#pragma unroll
    for (int i = 0; i < 16; i++) { v[i] = expf(v[i] - mx); sum += v[i]; }
#pragma unroll
    for (int off = 16; off >= 1; off >>= 1)
        sum += __shfl_xor_sync(0xffffffffu, sum, off);
    if (lane == 0) sm[wid] = sum;
    __syncthreads();
    sum = sm[0];
#pragma unroll
    for (int w = 1; w < 8; w++) sum += sm[w];
    float inv = 1.0f / sum;

#pragma unroll
    for (int i = 0; i < 4; i++) {
        float4 o = { to_tf32(v[4*i+0]*inv), to_tf32(v[4*i+1]*inv),
                     to_tf32(v[4*i+2]*inv), to_tf32(v[4*i+3]*inv) };
        p4[t + i * 256] = o;
    }
}

// ---------------------------------------------------------------------------
extern "C" void kernel_launch(void* const* d_in, const int* in_sizes, int n_in,
                              void* d_out, int out_size)
{
    const float* x  = (const float*)d_in[0];
    const float* Wq = (const float*)d_in[1];
    const float* bq = (const float*)d_in[2];
    const float* Wk = (const float*)d_in[3];
    const float* bk = (const float*)d_in[4];
    const float* Wv = (const float*)d_in[5];
    const float* bv = (const float*)d_in[6];
    const float* pb = (const float*)d_in[7];
    float* out = (float*)d_out;

    float *Q, *K, *V, *Vt, *Qe, *Ke, *Sm;
    cudaGetSymbolAddress((void**)&Q,  g_Q);
    cudaGetSymbolAddress((void**)&K,  g_K);
    cudaGetSymbolAddress((void**)&V,  g_V);
    cudaGetSymbolAddress((void**)&Vt, g_Vt);
    cudaGetSymbolAddress((void**)&Qe, g_Qe);
    cudaGetSymbolAddress((void**)&Ke, g_Ke);
    cudaGetSymbolAddress((void**)&Sm, g_S);

    cudaFuncSetAttribute(mma_nt_tf32,
                         cudaFuncAttributeMaxDynamicSharedMemorySize,
                         MMA_SMEM_BYTES);

    // 1) QKV projections (fp32 FFMA): C[8192,1024] = x @ W^T + b
    dim3 gProj(DIM / 128, MTOT / 128, 1);
    sgemm_nt<<<gProj, 256>>>(x, Wq, bq, Q, MTOT, DIM, DIM);
    sgemm_nt<<<gProj, 256>>>(x, Wk, bk, K, MTOT, DIM, DIM);
    sgemm_nt<<<gProj, 256>>>(x, Wv, bv, V, MTOT, DIM, DIM);

    // 2) theta -> [cos | sin] (tf32-rounded)
    theta_kernel<<<(MTOT * DIM) / 256, 256>>>(Q, K, pb, Qe, Ke);

    // 3) V transpose (+ tf32 round) for PV tensor GEMM
    dim3 gT(DIM / 32, SEQ / 32, BATCH);
    transpose_round<<<gT, dim3(32, 8)>>>(V, Vt);

    // 4) sim = Qe @ Ke^T per batch (tf32 mma.sync)
    dim3 gSim(SEQ / 128, SEQ / 128, BATCH);
    mma_nt_tf32<<<gSim, 256, MMA_SMEM_BYTES>>>(
        Qe, Ke, Sm, SEQ, DE,
        (size_t)SEQ * DE, (size_t)SEQ * DE, (size_t)SEQ * SEQ);

    // 5) softmax(sim / 32) rows (tf32-rounded weights)
    softmax_rows<<<BATCH * SEQ, 256>>>(Sm);

    // 6) out = weights @ Vt^T per batch (tf32 mma.sync)
    dim3 gPV(DIM / 128, SEQ / 128, BATCH);
    mma_nt_tf32<<<gPV, 256, MMA_SMEM_BYTES>>>(
        Sm, Vt, out, DIM, SEQ,
        (size_t)SEQ * SEQ, (size_t)DIM * SEQ, (size_t)SEQ * DIM);
}